// round 2
// baseline (speedup 1.0000x reference)
#include <cuda_runtime.h>
#include <cuda_bf16.h>

#define H 64
#define K 256
#define TPB 512
#define CT_STRIDE 260            // floats per h-row of cT: 1040 B (16B aligned)
#define XS_STRIDE 65             // padded x-tile row: conflict-free per-thread reads

// dynamic smem layout (floats):
//   [0, 64*260)                  cT   : centers transposed, cT[h*260 + k]
//   [64*260, +256)               c2h  : ||c_k||^2 (fp32, sequential-h sum)
//   [.., +512*65)                xs   : x tile, xs[p*65 + h]
#define CT_FLOATS   (64 * CT_STRIDE)
#define C2H_OFF     CT_FLOATS
#define XS_OFF      (CT_FLOATS + K)
#define SMEM_FLOATS (XS_OFF + TPB * XS_STRIDE)
#define SMEM_BYTES  (SMEM_FLOATS * 4)

__device__ __forceinline__ unsigned long long fma2(unsigned long long a,
                                                   unsigned long long b,
                                                   unsigned long long c) {
    unsigned long long d;
    asm("fma.rn.f32x2 %0, %1, %2, %3;" : "=l"(d) : "l"(a), "l"(b), "l"(c));
    return d;
}

__device__ __forceinline__ unsigned long long packdup(float x) {
    unsigned long long d;
    asm("mov.b64 %0, {%1, %1};" : "=l"(d) : "r"(__float_as_int(x)));
    return d;
}

__device__ __forceinline__ void unpack2(unsigned long long v, float& lo, float& hi) {
    int a, b;
    asm("mov.b64 {%0, %1}, %2;" : "=r"(a), "=r"(b) : "l"(v));
    lo = __int_as_float(a);
    hi = __int_as_float(b);
}

extern __shared__ float smem_dyn[];

__global__ __launch_bounds__(TPB, 1)
void LatentSpaceClustering_46797963657837_kernel(const float* __restrict__ x,
                                                 const float* __restrict__ c,
                                                 float* __restrict__ out, int n) {
    float* cT  = smem_dyn;
    float* c2h = smem_dyn + C2H_OFF;
    float* xs  = smem_dyn + XS_OFF;
    const int tid = threadIdx.x;

    // ---- stage centers transposed (coalesced global read, scattered STS) ----
    for (int i = tid; i < K * H / 4; i += TPB) {
        float4 v = ((const float4*)c)[i];
        int k = (i * 4) / H;
        int h = (i * 4) % H;
        cT[(h + 0) * CT_STRIDE + k] = v.x;
        cT[(h + 1) * CT_STRIDE + k] = v.y;
        cT[(h + 2) * CT_STRIDE + k] = v.z;
        cT[(h + 3) * CT_STRIDE + k] = v.w;
    }

    // ---- stage x tile (coalesced) ----
    {
        long long base_pt = (long long)blockIdx.x * TPB;
        const float* xblk = x + base_pt * H;
        for (int i = tid; i < TPB * H / 4; i += TPB) {
            int p = (i * 4) / H;
            int h = (i * 4) % H;
            float4 v = make_float4(0.f, 0.f, 0.f, 0.f);
            if (base_pt + p < n) v = ((const float4*)xblk)[i];
            float* xr = xs + p * XS_STRIDE + h;
            xr[0] = v.x; xr[1] = v.y; xr[2] = v.z; xr[3] = v.w;
        }
    }
    __syncthreads();

    // ---- ||c_k||^2 in fp32 (mul-then-add, sequential h, like jnp.sum(c*c)) ----
    if (tid < K) {
        float s = 0.f;
        #pragma unroll
        for (int h = 0; h < H; ++h) {
            float v = cT[h * CT_STRIDE + tid];
            s = __fadd_rn(s, __fmul_rn(v, v));
        }
        c2h[tid] = s;
    }
    __syncthreads();

    // ---- main: one point per thread, 32-k chunks, f32x2 dot accumulators ----
    const int pt = blockIdx.x * TPB + tid;
    const float* xrow = xs + tid * XS_STRIDE;

    // x2 = sum(x*x), fp32 sequential (common offset for all k)
    float x2 = 0.f;
    #pragma unroll
    for (int h = 0; h < H; ++h)
        x2 = __fadd_rn(x2, __fmul_rn(xrow[h], xrow[h]));

    float best = 3.402823466e+38f;
    int bestK = 0;

    for (int kc = 0; kc < K; kc += 32) {
        unsigned long long acc[16];
        #pragma unroll
        for (int j = 0; j < 16; ++j) acc[j] = 0ull;

        #pragma unroll 4
        for (int h = 0; h < H; ++h) {
            unsigned long long xp = packdup(xrow[h]);
            const float* crow = cT + h * CT_STRIDE + kc;
            #pragma unroll
            for (int j = 0; j < 8; ++j) {
                ulonglong2 cv = *(const ulonglong2*)(crow + 4 * j);  // c[k..k+3], broadcast LDS.128
                acc[2 * j]     = fma2(xp, cv.x, acc[2 * j]);
                acc[2 * j + 1] = fma2(xp, cv.y, acc[2 * j + 1]);
            }
        }

        // epilogue: d2 = (x2 + c2[k]) - 2*dot  (2*dot exact => fmaf is bit-identical
        // to the reference's separate mul+sub). Strict < keeps the first index.
        #pragma unroll
        for (int j = 0; j < 16; ++j) {
            float lo, hi;
            unpack2(acc[j], lo, hi);
            int k0 = kc + 2 * j;
            float d2a = __fmaf_rn(-2.0f, lo, __fadd_rn(x2, c2h[k0]));
            float d2b = __fmaf_rn(-2.0f, hi, __fadd_rn(x2, c2h[k0 + 1]));
            if (d2a < best) { best = d2a; bestK = k0; }
            if (d2b < best) { best = d2b; bestK = k0 + 1; }
        }
    }

    if (pt < n) out[pt] = (float)bestK;
}

extern "C" void kernel_launch(void* const* d_in, const int* in_sizes, int n_in,
                              void* d_out, int out_size) {
    const float* x = (const float*)d_in[0];
    const float* c = (const float*)d_in[1];
    int n = in_sizes[0] / H;

    cudaFuncSetAttribute(LatentSpaceClustering_46797963657837_kernel,
                         cudaFuncAttributeMaxDynamicSharedMemorySize, SMEM_BYTES);

    int grid = (n + TPB - 1) / TPB;
    LatentSpaceClustering_46797963657837_kernel<<<grid, TPB, SMEM_BYTES>>>(
        x, c, (float*)d_out, n);
}